// round 12
// baseline (speedup 1.0000x reference)
#include <cuda_runtime.h>
#include <cuda_fp16.h>
#include <math.h>
#include <stdint.h>

// ---------------------------------------------------------------------------
// TinyDiffusion MLP on GB300 — fp16 mma.sync (m16n8k16, f32 accum).
// Established: legacy mma.sync issue-rate ceiling ~0.25 HMMA/cyc/SM
// (tensor counter ~47%; tcgen05 blocked by toolchain). Mainloop at ceiling.
// This round: kill wave quantization on GEMM1/2 via 64x128 tiles
// (T=2048 -> 6.92 waves, loss ~20us vs ~139/55us at 128x128).
//   a0  = relu([x|tail] @ nw0^T + nb0)  K=20608  -> fp16   [64x128]
//   a1  = relu(a0 @ nw1^T + nb1)        K=4096   -> fp16   [64x128]
//   out =       a1 @ nw2^T + nb2        K=4096, N=20480 -> fp32 [128x128]
// BK=64 slab, 3-stage cp.async ring, 2 CTAs/SM, ldmatrix.x4, 144B rows.
// w1/w2 fp32->fp16 conversion rides GEMM1's spare CTA slots.
// ---------------------------------------------------------------------------

#define BATCH      4096
#define LATENT_DIM 20480
#define TAIL_DIM   128
#define IN_DIM     20608
#define HIDDEN     4096
#define TIME_DIM   64
#define COND_DIM   64

#define BK 64                    // halves per slab (= 4 k16 steps)
#define STAGES 3
#define ROWB 144                 // bytes per smem row: 128B data + 16B pad
#define GROUP_M 16
#define NCONV 80                 // converter CTAs appended to GEMM1

// fp16 scratch (device globals: allowed; runtime allocation is not)
__device__ __align__(16) __half g_w0[(size_t)HIDDEN * IN_DIM];
__device__ __align__(16) __half g_w1[(size_t)HIDDEN * HIDDEN];
__device__ __align__(16) __half g_w2[(size_t)LATENT_DIM * HIDDEN];
__device__ __align__(16) __half g_x [(size_t)BATCH * LATENT_DIM];
__device__ __align__(16) __half g_tail[BATCH * TAIL_DIM];
__device__ __align__(16) __half g_a0[(size_t)BATCH * HIDDEN];
__device__ __align__(16) __half g_a1[(size_t)BATCH * HIDDEN];

// ---------------- helpers ----------------
__device__ __forceinline__ uint32_t s2u(const void* p) {
    uint32_t a;
    asm("{ .reg .u64 t; cvta.to.shared.u64 t, %1; cvt.u32.u64 %0, t; }" : "=r"(a) : "l"(p));
    return a;
}
__device__ __forceinline__ void cp16(uint32_t dst, const void* src) {
    asm volatile("cp.async.cg.shared.global [%0], [%1], 16;" :: "r"(dst), "l"(src));
}
__device__ __forceinline__ void ldsm4(uint32_t* r, uint32_t addr) {
    asm volatile("ldmatrix.sync.aligned.m8n8.x4.shared.b16 {%0,%1,%2,%3}, [%4];"
                 : "=r"(r[0]), "=r"(r[1]), "=r"(r[2]), "=r"(r[3]) : "r"(addr));
}
__device__ __forceinline__ void mma16(float* c, const uint32_t* a, uint32_t b0, uint32_t b1) {
    asm volatile("mma.sync.aligned.m16n8k16.row.col.f32.f16.f16.f32 "
                 "{%0,%1,%2,%3}, {%4,%5,%6,%7}, {%8,%9}, {%0,%1,%2,%3};"
                 : "+f"(c[0]), "+f"(c[1]), "+f"(c[2]), "+f"(c[3])
                 : "r"(a[0]), "r"(a[1]), "r"(a[2]), "r"(a[3]), "r"(b0), "r"(b1));
}
__device__ __forceinline__ void conv_range(const float* __restrict__ in,
                                           __half* __restrict__ out,
                                           size_t n4, int cid, int nctas)
{
    size_t i = (size_t)cid * blockDim.x + threadIdx.x;
    size_t stride = (size_t)nctas * blockDim.x;
    for (; i < n4; i += stride) {
        float4 v = __ldcs(reinterpret_cast<const float4*>(in) + i);
        __half2 h0 = __floats2half2_rn(v.x, v.y);
        __half2 h1 = __floats2half2_rn(v.z, v.w);
        uint32_t u0 = *reinterpret_cast<uint32_t*>(&h0);
        uint32_t u1 = *reinterpret_cast<uint32_t*>(&h1);
        __stcs(reinterpret_cast<uint2*>(out) + i, make_uint2(u0, u1));
    }
}

// ---------------------------------------------------------------------------
// fp32 -> fp16 (rne), streaming, grid-stride over float4
// ---------------------------------------------------------------------------
__global__ void f2h_kernel(const float* __restrict__ in, __half* __restrict__ out, size_t n4)
{
    size_t i = blockIdx.x * (size_t)blockDim.x + threadIdx.x;
    size_t stride = (size_t)gridDim.x * blockDim.x;
    for (; i < n4; i += stride) {
        float4 v = __ldcs(reinterpret_cast<const float4*>(in) + i);
        __half2 h0 = __floats2half2_rn(v.x, v.y);
        __half2 h1 = __floats2half2_rn(v.z, v.w);
        uint32_t u0 = *reinterpret_cast<uint32_t*>(&h0);
        uint32_t u1 = *reinterpret_cast<uint32_t*>(&h1);
        __stcs(reinterpret_cast<uint2*>(out) + i, make_uint2(u0, u1));
    }
}

// ---------------------------------------------------------------------------
// time features + 2-layer time MLP + digit embedding -> fp16 tail [B,128]
// ---------------------------------------------------------------------------
__global__ void time_tail_kernel(const int* __restrict__ timesteps,
                                 const int* __restrict__ digits,
                                 const int* __restrict__ num_steps_p,
                                 const float* __restrict__ emb_table,
                                 const float* __restrict__ tw0,
                                 const float* __restrict__ tb0,
                                 const float* __restrict__ tw1,
                                 const float* __restrict__ tb1,
                                 __half* __restrict__ tail)
{
    const int row = blockIdx.x;
    const int j   = threadIdx.x;
    __shared__ float h[TIME_DIM];

    const int ns = num_steps_p[0];
    const float denom = (float)((ns - 1) > 1 ? (ns - 1) : 1);
    const float t = (float)timesteps[row] / denom;
    const float pi = 3.14159265358979323846f;
    const float f0 = t, f1 = t * t, f2 = sinf(pi * t), f3 = cosf(pi * t);

    float v = tb0[j] + f0 * tw0[j * 4 + 0] + f1 * tw0[j * 4 + 1]
                     + f2 * tw0[j * 4 + 2] + f3 * tw0[j * 4 + 3];
    h[j] = fmaxf(v, 0.0f);
    __syncthreads();

    float acc = tb1[j];
    #pragma unroll 8
    for (int i = 0; i < TIME_DIM; i++) acc += h[i] * tw1[j * TIME_DIM + i];

    const int d = digits[row];
    tail[row * TAIL_DIM + j]            = __float2half_rn(emb_table[d * COND_DIM + j]);
    tail[row * TAIL_DIM + COND_DIM + j] = __float2half_rn(acc);
}

// ---------------------------------------------------------------------------
// fp16 HMMA GEMM: C[M,N] = act(A[M,K] @ W[N,K]^T + bias)
// A,W fp16; bias fp32; C fp16 (HOUT) or fp32.
// 8 warps (2x4): warp tile (BMT/2) x (BNT/4). BK=64 slab, 3-stage ring,
// 2 CTAs/SM. CONV: blocks past gemm_blocks convert w1/w2 fp32->fp16.
// ---------------------------------------------------------------------------
template<int BMT, int BNT, bool FUSE, bool RELU, bool HOUT, bool CONV>
__global__ __launch_bounds__(256, 2)
void gemm_h(const __half* __restrict__ A,
            const __half* __restrict__ tailp,
            const __half* __restrict__ W,
            const float* __restrict__ bias,
            void* __restrict__ Cout,
            int M, int N, int K, int lda,
            int gemm_blocks,
            const float* __restrict__ cw1s, __half* __restrict__ cw1d, size_t cn1,
            const float* __restrict__ cw2s, __half* __restrict__ cw2d, size_t cn2)
{
    if (CONV && (int)blockIdx.x >= gemm_blocks) {
        const int cid = blockIdx.x - gemm_blocks;
        conv_range(cw1s, cw1d, cn1, cid, NCONV);
        conv_range(cw2s, cw2d, cn2, cid, NCONV);
        return;
    }

    constexpr int WMEXT = BMT / 2;        // warp M extent (32 or 64)
    constexpr int MT    = BMT / 32;       // m16 tiles per warp (2 or 4)
    constexpr int WN    = BNT / 4;        // warp N extent (32)
    constexpr int NTREG = WN / 8;         // n8 acc groups (4)
    constexpr int NLDSB = WN / 16;        // B ldsm4 per ks (2)
    constexpr int ABYT  = BMT * ROWB;
    constexpr int STGB  = ABYT + BNT * ROWB;
    constexpr int ACH   = BMT / 32;       // A cp.async per thread (2 or 4)
    constexpr int BCH   = BNT / 32;       // B cp.async per thread (4)

    extern __shared__ char smem_raw[];
    const uint32_t smem_u = s2u(smem_raw);

    const int tid  = threadIdx.x;
    const int wid  = tid >> 5;
    const int lane = tid & 31;
    const int wm   = wid >> 2;            // 0..1
    const int wn   = wid & 3;             // 0..3

    // ldmatrix lane mapping: row-in-16, chunk(16B)-in-2
    const int lrow = (lane & 7) + ((lane >> 3) & 1) * 8;
    const int lch  = lane >> 4;           // 0..1

    // grid swizzle
    const int numPidM = M / BMT;
    const int numPidN = N / BNT;
    int pid = blockIdx.x;
    const int widthn  = GROUP_M * numPidN;
    const int groupId = pid / widthn;
    const int firstM  = groupId * GROUP_M;
    const int gszM    = min(numPidM - firstM, GROUP_M);
    const int pidm    = firstM + (pid % gszM);
    const int pidn    = (pid % widthn) / gszM;

    const int rowA0 = pidm * BMT;
    const int rowB0 = pidn * BNT;
    const int NSLAB = K / BK;

    float acc[MT][NTREG][4];
    #pragma unroll
    for (int mt = 0; mt < MT; mt++)
        #pragma unroll
        for (int nt = 0; nt < NTREG; nt++)
            #pragma unroll
            for (int q = 0; q < 4; q++) acc[mt][nt][q] = 0.0f;

    auto issue_slab = [&](int sl) {
        if (sl >= NSLAB) return;
        const uint32_t base = smem_u + (sl % STAGES) * STGB;
        const int k0 = sl * BK;                       // halves
        #pragma unroll
        for (int j = 0; j < ACH; j++) {
            const int id = tid + j * 256;
            const int r = id >> 3, c = id & 7;
            const __half* src;
            if (FUSE && k0 >= lda)
                src = tailp + (size_t)(rowA0 + r) * TAIL_DIM + (k0 - lda) + c * 8;
            else
                src = A + (size_t)(rowA0 + r) * lda + k0 + c * 8;
            cp16(base + r * ROWB + c * 16, src);
        }
        #pragma unroll
        for (int j = 0; j < BCH; j++) {
            const int id = tid + j * 256;
            const int r = id >> 3, c = id & 7;
            const __half* src = W + (size_t)(rowB0 + r) * K + k0 + c * 8;
            cp16(base + ABYT + r * ROWB + c * 16, src);
        }
    };

    #pragma unroll
    for (int s = 0; s < STAGES - 1; s++) {
        issue_slab(s);
        asm volatile("cp.async.commit_group;" ::: "memory");
    }

    for (int i = 0; i < NSLAB; i++) {
        asm volatile("cp.async.wait_group %0;" :: "n"(STAGES - 2) : "memory");
        __syncthreads();

        issue_slab(i + STAGES - 1);
        asm volatile("cp.async.commit_group;" ::: "memory");

        const uint32_t sb = smem_u + (i % STAGES) * STGB;

        #pragma unroll
        for (int ks = 0; ks < 4; ks++) {
            uint32_t af[MT][4], bf[NLDSB][4];
            #pragma unroll
            for (int mt = 0; mt < MT; mt++)
                ldsm4(af[mt], sb + (wm * WMEXT + mt * 16 + lrow) * ROWB + ks * 32 + lch * 16);
            #pragma unroll
            for (int p = 0; p < NLDSB; p++)
                ldsm4(bf[p], sb + ABYT + (wn * WN + p * 16 + lrow) * ROWB + ks * 32 + lch * 16);
            #pragma unroll
            for (int mt = 0; mt < MT; mt++)
                #pragma unroll
                for (int nt = 0; nt < NTREG; nt++)
                    mma16(acc[mt][nt], af[mt], bf[nt >> 1][nt & 1], bf[nt >> 1][(nt & 1) + 2]);
        }
    }

    // epilogue: acc[mt][p*2+q] covers cols wn*WN + p*16 + q*8
    const int lr = lane >> 2, lc = lane & 3;
    #pragma unroll
    for (int nt = 0; nt < NTREG; nt++) {
        const int col = rowB0 + wn * WN + (nt >> 1) * 16 + (nt & 1) * 8 + lc * 2;
        const float2 bv = *reinterpret_cast<const float2*>(bias + col);
        #pragma unroll
        for (int mt = 0; mt < MT; mt++) {
            const int r0 = rowA0 + wm * WMEXT + mt * 16 + lr;
            float x0 = acc[mt][nt][0] + bv.x, x1 = acc[mt][nt][1] + bv.y;
            float x2 = acc[mt][nt][2] + bv.x, x3 = acc[mt][nt][3] + bv.y;
            if (RELU) {
                x0 = fmaxf(x0, 0.0f); x1 = fmaxf(x1, 0.0f);
                x2 = fmaxf(x2, 0.0f); x3 = fmaxf(x3, 0.0f);
            }
            if (HOUT) {
                __half* C = (__half*)Cout;
                __half2 h0 = __floats2half2_rn(x0, x1);
                __half2 h1 = __floats2half2_rn(x2, x3);
                *reinterpret_cast<__half2*>(C + (size_t)r0 * N + col)       = h0;
                *reinterpret_cast<__half2*>(C + (size_t)(r0 + 8) * N + col) = h1;
            } else {
                float* C = (float*)Cout;
                *reinterpret_cast<float2*>(C + (size_t)r0 * N + col)       = make_float2(x0, x1);
                *reinterpret_cast<float2*>(C + (size_t)(r0 + 8) * N + col) = make_float2(x2, x3);
            }
        }
    }
}

// ---------------------------------------------------------------------------
// Launch
// ---------------------------------------------------------------------------
extern "C" void kernel_launch(void* const* d_in, const int* in_sizes, int n_in,
                              void* d_out, int out_size)
{
    const float* noisy     = (const float*)d_in[0];
    const int*   digits    = (const int*)  d_in[1];
    const int*   timesteps = (const int*)  d_in[2];
    const int*   num_steps = (const int*)  d_in[3];
    const float* emb       = (const float*)d_in[4];
    const float* tw0       = (const float*)d_in[5];
    const float* tb0       = (const float*)d_in[6];
    const float* tw1       = (const float*)d_in[7];
    const float* tb1       = (const float*)d_in[8];
    const float* nw0       = (const float*)d_in[9];
    const float* nb0       = (const float*)d_in[10];
    const float* nw1       = (const float*)d_in[11];
    const float* nb1       = (const float*)d_in[12];
    const float* nw2       = (const float*)d_in[13];
    const float* nb2       = (const float*)d_in[14];
    float*       out       = (float*)d_out;

    __half *w0, *w1, *w2, *x, *tail, *a0, *a1;
    cudaGetSymbolAddress((void**)&w0,   g_w0);
    cudaGetSymbolAddress((void**)&w1,   g_w1);
    cudaGetSymbolAddress((void**)&w2,   g_w2);
    cudaGetSymbolAddress((void**)&x,    g_x);
    cudaGetSymbolAddress((void**)&tail, g_tail);
    cudaGetSymbolAddress((void**)&a0,   g_a0);
    cudaGetSymbolAddress((void**)&a1,   g_a1);

    constexpr int SMEM_64_128  = STAGES * ((64  + 128) * ROWB);   // 82944
    constexpr int SMEM_128_128 = STAGES * ((128 + 128) * ROWB);   // 110592

    cudaFuncSetAttribute(gemm_h<64, 128, true,  true,  true,  true >,
                         cudaFuncAttributeMaxDynamicSharedMemorySize, SMEM_64_128);
    cudaFuncSetAttribute(gemm_h<64, 128, false, true,  true,  false>,
                         cudaFuncAttributeMaxDynamicSharedMemorySize, SMEM_64_128);
    cudaFuncSetAttribute(gemm_h<128, 128, false, false, false, false>,
                         cudaFuncAttributeMaxDynamicSharedMemorySize, SMEM_128_128);

    // serial pre-pass: only what GEMM1 needs (w0, x); w1/w2 convert inside GEMM1
    f2h_kernel<<<2048, 256>>>(nw0,   w0, (size_t)HIDDEN * IN_DIM / 4);
    f2h_kernel<<<2048, 256>>>(noisy, x,  (size_t)BATCH * LATENT_DIM / 4);

    time_tail_kernel<<<BATCH, TIME_DIM>>>(timesteps, digits, num_steps,
                                          emb, tw0, tb0, tw1, tb1, tail);

    // a0 = relu([x|tail] @ nw0^T + nb0); +80 converter CTAs fill spare slots
    {
        const int gb = (BATCH / 64) * (HIDDEN / 128);   // 2048
        gemm_h<64, 128, true, true, true, true><<<gb + NCONV, 256, SMEM_64_128>>>(
            x, tail, w0, nb0, a0, BATCH, HIDDEN, IN_DIM, LATENT_DIM,
            gb,
            nw1, w1, (size_t)HIDDEN * HIDDEN / 4,
            nw2, w2, (size_t)LATENT_DIM * HIDDEN / 4);
    }

    // a1 = relu(a0 @ nw1^T + nb1)
    {
        const int gb = (BATCH / 64) * (HIDDEN / 128);   // 2048
        gemm_h<64, 128, false, true, true, false><<<gb, 256, SMEM_64_128>>>(
            a0, nullptr, w1, nb1, a1, BATCH, HIDDEN, HIDDEN, HIDDEN,
            gb, nullptr, nullptr, 0, nullptr, nullptr, 0);
    }

    // out = a1 @ nw2^T + nb2
    {
        const int gb = (BATCH / 128) * (LATENT_DIM / 128);   // 5120
        gemm_h<128, 128, false, false, false, false><<<gb, 256, SMEM_128_128>>>(
            a1, nullptr, w2, nb2, out, BATCH, LATENT_DIM, HIDDEN, HIDDEN,
            gb, nullptr, nullptr, 0, nullptr, nullptr, 0);
    }
}

// round 13
// speedup vs baseline: 1.0733x; 1.0733x over previous
#include <cuda_runtime.h>
#include <cuda_fp16.h>
#include <math.h>
#include <stdint.h>

// ---------------------------------------------------------------------------
// TinyDiffusion MLP on GB300 — fp16 mma.sync (m16n8k16, f32 accum).
// Mainloop pinned at the sm_103 legacy-mma issue ceiling (~47% tensor counter;
// tcgen05 blocked by toolchain). R10 config restored (best: 5118us).
// This round: fuse the serial prefix (f2h(w0) + f2h(x) + time_tail) into ONE
// launch via block-range partitioning -> all prepass work runs concurrently.
//   a0  = relu([x|tail] @ nw0^T + nb0)  K=20608  -> fp16   [128x128, 2 CTA/SM]
//   a1  = relu(a0 @ nw1^T + nb1)        K=4096   -> fp16   [128x128]
//   out =       a1 @ nw2^T + nb2        K=4096, N=20480 -> fp32 [128x128]
// BK=64 slab, 3-stage cp.async ring, ldmatrix.x4, 144B rows (conflict-free).
// w1/w2 fp32->fp16 conversion rides GEMM1's spare CTA slots.
// ---------------------------------------------------------------------------

#define BATCH      4096
#define LATENT_DIM 20480
#define TAIL_DIM   128
#define IN_DIM     20608
#define HIDDEN     4096
#define TIME_DIM   64
#define COND_DIM   64

#define BM 128
#define BN 128
#define BK 64                    // halves per slab (= 4 k16 steps)
#define STAGES 3
#define ROWB 144                 // bytes per smem row: 128B data + 16B pad
#define A_BYTES (BM * ROWB)      // 18432
#define B_BYTES (BN * ROWB)      // 18432
#define STG_BYTES (A_BYTES + B_BYTES)   // 36864
#define SMEM_DYN (STAGES * STG_BYTES)   // 110592  -> 2 CTAs/SM
#define GROUP_M 16
#define NCONV 80                 // converter CTAs appended to GEMM1

// prepass block ranges
#define PRE_W0_BLOCKS   1536
#define PRE_X_BLOCKS    512
#define PRE_TAIL_BLOCKS (BATCH / 4)     // 4 rows per 256-thread block
#define PRE_TOTAL (PRE_W0_BLOCKS + PRE_X_BLOCKS + PRE_TAIL_BLOCKS)

// fp16 scratch (device globals: allowed; runtime allocation is not)
__device__ __align__(16) __half g_w0[(size_t)HIDDEN * IN_DIM];
__device__ __align__(16) __half g_w1[(size_t)HIDDEN * HIDDEN];
__device__ __align__(16) __half g_w2[(size_t)LATENT_DIM * HIDDEN];
__device__ __align__(16) __half g_x [(size_t)BATCH * LATENT_DIM];
__device__ __align__(16) __half g_tail[BATCH * TAIL_DIM];
__device__ __align__(16) __half g_a0[(size_t)BATCH * HIDDEN];
__device__ __align__(16) __half g_a1[(size_t)BATCH * HIDDEN];

// ---------------- helpers ----------------
__device__ __forceinline__ uint32_t s2u(const void* p) {
    uint32_t a;
    asm("{ .reg .u64 t; cvta.to.shared.u64 t, %1; cvt.u32.u64 %0, t; }" : "=r"(a) : "l"(p));
    return a;
}
__device__ __forceinline__ void cp16(uint32_t dst, const void* src) {
    asm volatile("cp.async.cg.shared.global [%0], [%1], 16;" :: "r"(dst), "l"(src));
}
__device__ __forceinline__ void ldsm4(uint32_t* r, uint32_t addr) {
    asm volatile("ldmatrix.sync.aligned.m8n8.x4.shared.b16 {%0,%1,%2,%3}, [%4];"
                 : "=r"(r[0]), "=r"(r[1]), "=r"(r[2]), "=r"(r[3]) : "r"(addr));
}
__device__ __forceinline__ void mma16(float* c, const uint32_t* a, uint32_t b0, uint32_t b1) {
    asm volatile("mma.sync.aligned.m16n8k16.row.col.f32.f16.f16.f32 "
                 "{%0,%1,%2,%3}, {%4,%5,%6,%7}, {%8,%9}, {%0,%1,%2,%3};"
                 : "+f"(c[0]), "+f"(c[1]), "+f"(c[2]), "+f"(c[3])
                 : "r"(a[0]), "r"(a[1]), "r"(a[2]), "r"(a[3]), "r"(b0), "r"(b1));
}
__device__ __forceinline__ void conv_range(const float* __restrict__ in,
                                           __half* __restrict__ out,
                                           size_t n4, int cid, int nctas)
{
    size_t i = (size_t)cid * blockDim.x + threadIdx.x;
    size_t stride = (size_t)nctas * blockDim.x;
    for (; i < n4; i += stride) {
        float4 v = __ldcs(reinterpret_cast<const float4*>(in) + i);
        __half2 h0 = __floats2half2_rn(v.x, v.y);
        __half2 h1 = __floats2half2_rn(v.z, v.w);
        uint32_t u0 = *reinterpret_cast<uint32_t*>(&h0);
        uint32_t u1 = *reinterpret_cast<uint32_t*>(&h1);
        __stcs(reinterpret_cast<uint2*>(out) + i, make_uint2(u0, u1));
    }
}

// ---------------------------------------------------------------------------
// Fused prepass (one launch, 256 threads/block):
//   blocks [0, PRE_W0_BLOCKS):                         w0 fp32 -> fp16
//   blocks [PRE_W0_BLOCKS, +PRE_X_BLOCKS):             noisy -> fp16
//   blocks [.., +PRE_TAIL_BLOCKS):                     time-MLP + embed tail
// ---------------------------------------------------------------------------
__global__ __launch_bounds__(256)
void prepass_kernel(const float* __restrict__ nw0,  __half* __restrict__ w0,
                    const float* __restrict__ noisy, __half* __restrict__ x,
                    const int* __restrict__ timesteps,
                    const int* __restrict__ digits,
                    const int* __restrict__ num_steps_p,
                    const float* __restrict__ emb_table,
                    const float* __restrict__ tw0,
                    const float* __restrict__ tb0,
                    const float* __restrict__ tw1,
                    const float* __restrict__ tb1,
                    __half* __restrict__ tail)
{
    const int b = blockIdx.x;
    if (b < PRE_W0_BLOCKS) {
        conv_range(nw0, w0, (size_t)HIDDEN * IN_DIM / 4, b, PRE_W0_BLOCKS);
        return;
    }
    if (b < PRE_W0_BLOCKS + PRE_X_BLOCKS) {
        conv_range(noisy, x, (size_t)BATCH * LATENT_DIM / 4,
                   b - PRE_W0_BLOCKS, PRE_X_BLOCKS);
        return;
    }

    // tail: 4 rows per block, 64 threads per row
    const int tb4  = b - PRE_W0_BLOCKS - PRE_X_BLOCKS;   // 0..1023
    const int sub  = threadIdx.x >> 6;                   // 0..3 row-in-block
    const int j    = threadIdx.x & 63;                   // 0..63
    const int row  = tb4 * 4 + sub;

    __shared__ float h[4][TIME_DIM];

    const int ns = num_steps_p[0];
    const float denom = (float)((ns - 1) > 1 ? (ns - 1) : 1);
    const float t = (float)timesteps[row] / denom;
    const float pi = 3.14159265358979323846f;
    const float f0 = t, f1 = t * t, f2 = sinf(pi * t), f3 = cosf(pi * t);

    float v = tb0[j] + f0 * tw0[j * 4 + 0] + f1 * tw0[j * 4 + 1]
                     + f2 * tw0[j * 4 + 2] + f3 * tw0[j * 4 + 3];
    h[sub][j] = fmaxf(v, 0.0f);
    __syncthreads();

    float acc = tb1[j];
    #pragma unroll 8
    for (int i = 0; i < TIME_DIM; i++) acc += h[sub][i] * tw1[j * TIME_DIM + i];

    const int d = digits[row];
    tail[row * TAIL_DIM + j]            = __float2half_rn(emb_table[d * COND_DIM + j]);
    tail[row * TAIL_DIM + COND_DIM + j] = __float2half_rn(acc);
}

// ---------------------------------------------------------------------------
// fp16 HMMA GEMM: C[M,N] = act(A[M,K] @ W[N,K]^T + bias)
// A,W fp16; bias fp32; C fp16 (HOUT) or fp32.
// 8 warps (2x4), warp tile 64x32, BK=64 slab, 3-stage ring, 2 CTAs/SM.
// CONV: blocks past gemm_blocks run w1/w2 fp32->fp16 conversion instead.
// ---------------------------------------------------------------------------
template<bool FUSE, bool RELU, bool HOUT, bool CONV>
__global__ __launch_bounds__(256, 2)
void gemm_h(const __half* __restrict__ A,
            const __half* __restrict__ tailp,
            const __half* __restrict__ W,
            const float* __restrict__ bias,
            void* __restrict__ Cout,
            int M, int N, int K, int lda,
            int gemm_blocks,
            const float* __restrict__ cw1s, __half* __restrict__ cw1d, size_t cn1,
            const float* __restrict__ cw2s, __half* __restrict__ cw2d, size_t cn2)
{
    if (CONV && (int)blockIdx.x >= gemm_blocks) {
        const int cid = blockIdx.x - gemm_blocks;
        conv_range(cw1s, cw1d, cn1, cid, NCONV);
        conv_range(cw2s, cw2d, cn2, cid, NCONV);
        return;
    }

    extern __shared__ char smem_raw[];
    const uint32_t smem_u = s2u(smem_raw);

    const int tid  = threadIdx.x;
    const int wid  = tid >> 5;
    const int lane = tid & 31;
    const int wm   = wid >> 2;            // 0..1  (64 rows)
    const int wn   = wid & 3;             // 0..3  (32 cols)

    // ldmatrix lane mapping: row-in-16, chunk(16B)-in-2
    const int lrow = (lane & 7) + ((lane >> 3) & 1) * 8;
    const int lch  = lane >> 4;           // 0..1

    // grid swizzle
    const int numPidM = M / BM;
    const int numPidN = N / BN;
    int pid = blockIdx.x;
    const int widthn  = GROUP_M * numPidN;
    const int groupId = pid / widthn;
    const int firstM  = groupId * GROUP_M;
    const int gszM    = min(numPidM - firstM, GROUP_M);
    const int pidm    = firstM + (pid % gszM);
    const int pidn    = (pid % widthn) / gszM;

    const int rowA0 = pidm * BM;
    const int rowB0 = pidn * BN;
    const int NSLAB = K / BK;

    float acc[4][4][4];
    #pragma unroll
    for (int mt = 0; mt < 4; mt++)
        #pragma unroll
        for (int nt = 0; nt < 4; nt++)
            #pragma unroll
            for (int q = 0; q < 4; q++) acc[mt][nt][q] = 0.0f;

    // cp.async mapping: A 1024 chunks (4/thread), B 1024 chunks (4/thread)
    auto issue_slab = [&](int sl) {
        if (sl >= NSLAB) return;
        const uint32_t base = smem_u + (sl % STAGES) * STG_BYTES;
        const int k0 = sl * BK;                       // halves
        #pragma unroll
        for (int j = 0; j < 4; j++) {
            const int id = tid + j * 256;
            const int r = id >> 3, c = id & 7;
            const __half* src;
            if (FUSE && k0 >= lda)
                src = tailp + (size_t)(rowA0 + r) * TAIL_DIM + (k0 - lda) + c * 8;
            else
                src = A + (size_t)(rowA0 + r) * lda + k0 + c * 8;
            cp16(base + r * ROWB + c * 16, src);
        }
        #pragma unroll
        for (int j = 0; j < 4; j++) {
            const int id = tid + j * 256;
            const int r = id >> 3, c = id & 7;
            const __half* src = W + (size_t)(rowB0 + r) * K + k0 + c * 8;
            cp16(base + A_BYTES + r * ROWB + c * 16, src);
        }
    };

    #pragma unroll
    for (int s = 0; s < STAGES - 1; s++) {
        issue_slab(s);
        asm volatile("cp.async.commit_group;" ::: "memory");
    }

    for (int i = 0; i < NSLAB; i++) {
        asm volatile("cp.async.wait_group %0;" :: "n"(STAGES - 2) : "memory");
        __syncthreads();

        issue_slab(i + STAGES - 1);
        asm volatile("cp.async.commit_group;" ::: "memory");

        const uint32_t sb = smem_u + (i % STAGES) * STG_BYTES;

        #pragma unroll
        for (int ks = 0; ks < 4; ks++) {
            uint32_t af[4][4], bf[2][4];
            #pragma unroll
            for (int mt = 0; mt < 4; mt++)
                ldsm4(af[mt], sb + (wm * 64 + mt * 16 + lrow) * ROWB + ks * 32 + lch * 16);
            #pragma unroll
            for (int p = 0; p < 2; p++)
                ldsm4(bf[p], sb + A_BYTES + (wn * 32 + p * 16 + lrow) * ROWB + ks * 32 + lch * 16);
            #pragma unroll
            for (int mt = 0; mt < 4; mt++)
                #pragma unroll
                for (int nt = 0; nt < 4; nt++)
                    mma16(acc[mt][nt], af[mt], bf[nt >> 1][nt & 1], bf[nt >> 1][(nt & 1) + 2]);
        }
    }

    // epilogue: acc[mt][p*2+q] covers cols wn*32 + p*16 + q*8
    const int lr = lane >> 2, lc = lane & 3;
    #pragma unroll
    for (int nt = 0; nt < 4; nt++) {
        const int col = rowB0 + wn * 32 + (nt >> 1) * 16 + (nt & 1) * 8 + lc * 2;
        const float2 bv = *reinterpret_cast<const float2*>(bias + col);
        #pragma unroll
        for (int mt = 0; mt < 4; mt++) {
            const int r0 = rowA0 + wm * 64 + mt * 16 + lr;
            float x0 = acc[mt][nt][0] + bv.x, x1 = acc[mt][nt][1] + bv.y;
            float x2 = acc[mt][nt][2] + bv.x, x3 = acc[mt][nt][3] + bv.y;
            if (RELU) {
                x0 = fmaxf(x0, 0.0f); x1 = fmaxf(x1, 0.0f);
                x2 = fmaxf(x2, 0.0f); x3 = fmaxf(x3, 0.0f);
            }
            if (HOUT) {
                __half* C = (__half*)Cout;
                __half2 h0 = __floats2half2_rn(x0, x1);
                __half2 h1 = __floats2half2_rn(x2, x3);
                *reinterpret_cast<__half2*>(C + (size_t)r0 * N + col)       = h0;
                *reinterpret_cast<__half2*>(C + (size_t)(r0 + 8) * N + col) = h1;
            } else {
                float* C = (float*)Cout;
                *reinterpret_cast<float2*>(C + (size_t)r0 * N + col)       = make_float2(x0, x1);
                *reinterpret_cast<float2*>(C + (size_t)(r0 + 8) * N + col) = make_float2(x2, x3);
            }
        }
    }
}

// ---------------------------------------------------------------------------
// Launch
// ---------------------------------------------------------------------------
extern "C" void kernel_launch(void* const* d_in, const int* in_sizes, int n_in,
                              void* d_out, int out_size)
{
    const float* noisy     = (const float*)d_in[0];
    const int*   digits    = (const int*)  d_in[1];
    const int*   timesteps = (const int*)  d_in[2];
    const int*   num_steps = (const int*)  d_in[3];
    const float* emb       = (const float*)d_in[4];
    const float* tw0       = (const float*)d_in[5];
    const float* tb0       = (const float*)d_in[6];
    const float* tw1       = (const float*)d_in[7];
    const float* tb1       = (const float*)d_in[8];
    const float* nw0       = (const float*)d_in[9];
    const float* nb0       = (const float*)d_in[10];
    const float* nw1       = (const float*)d_in[11];
    const float* nb1       = (const float*)d_in[12];
    const float* nw2       = (const float*)d_in[13];
    const float* nb2       = (const float*)d_in[14];
    float*       out       = (float*)d_out;

    __half *w0, *w1, *w2, *x, *tail, *a0, *a1;
    cudaGetSymbolAddress((void**)&w0,   g_w0);
    cudaGetSymbolAddress((void**)&w1,   g_w1);
    cudaGetSymbolAddress((void**)&w2,   g_w2);
    cudaGetSymbolAddress((void**)&x,    g_x);
    cudaGetSymbolAddress((void**)&tail, g_tail);
    cudaGetSymbolAddress((void**)&a0,   g_a0);
    cudaGetSymbolAddress((void**)&a1,   g_a1);

    cudaFuncSetAttribute(gemm_h<true,  true,  true,  true >, cudaFuncAttributeMaxDynamicSharedMemorySize, SMEM_DYN);
    cudaFuncSetAttribute(gemm_h<false, true,  true,  false>, cudaFuncAttributeMaxDynamicSharedMemorySize, SMEM_DYN);
    cudaFuncSetAttribute(gemm_h<false, false, false, false>, cudaFuncAttributeMaxDynamicSharedMemorySize, SMEM_DYN);

    // fused prepass: w0 conversion + x conversion + tail MLP, one launch
    prepass_kernel<<<PRE_TOTAL, 256>>>(nw0, w0, noisy, x,
                                       timesteps, digits, num_steps,
                                       emb, tw0, tb0, tw1, tb1, tail);

    // a0 = relu([x|tail] @ nw0^T + nb0); +80 converter CTAs fill spare slots
    {
        const int gb = (BATCH / BM) * (HIDDEN / BN);   // 1024
        gemm_h<true, true, true, true><<<gb + NCONV, 256, SMEM_DYN>>>(
            x, tail, w0, nb0, a0, BATCH, HIDDEN, IN_DIM, LATENT_DIM,
            gb,
            nw1, w1, (size_t)HIDDEN * HIDDEN / 4,
            nw2, w2, (size_t)LATENT_DIM * HIDDEN / 4);
    }

    // a1 = relu(a0 @ nw1^T + nb1)
    {
        const int gb = (BATCH / BM) * (HIDDEN / BN);   // 1024
        gemm_h<false, true, true, false><<<gb, 256, SMEM_DYN>>>(
            a0, nullptr, w1, nb1, a1, BATCH, HIDDEN, HIDDEN, HIDDEN,
            gb, nullptr, nullptr, 0, nullptr, nullptr, 0);
    }

    // out = a1 @ nw2^T + nb2
    {
        const int gb = (BATCH / BM) * (LATENT_DIM / BN);   // 5120
        gemm_h<false, false, false, false><<<gb, 256, SMEM_DYN>>>(
            a1, nullptr, w2, nb2, out, BATCH, LATENT_DIM, HIDDEN, HIDDEN,
            gb, nullptr, nullptr, 0, nullptr, nullptr, 0);
    }
}